// round 4
// baseline (speedup 1.0000x reference)
#include <cuda_runtime.h>

// Fused spiking conv2d (T=128, Cin=16, Cout=64, 64x64, pad=1) + LIF scan.
// Thread = 2 adjacent-w pixels x 2 couts (doubled warp count vs R3 for latency
// cover), membrane state in registers across t. x tile staged to smem per
// timestep via double-buffered cp.async; halos zero-initialized once.
// Packed fma.rn.f32x2, exact (cin,kh,kw) order, (conv+b) then (state+conv)
// rounding -> bitwise-identical to the reference.

#define T_STEPS 128
#define CIN     16
#define HH      64
#define WWID    64
#define COUT    64

#define ROWS_S  18              // 16 rows + top/bottom halo
#define COLS_S  40              // fetch span wt-4 .. wt+35 (16B aligned)
#define BUF_FLOATS (CIN * ROWS_S * COLS_S)   // 11520 floats per buffer
#define CHUNKS_PER_T (CIN * ROWS_S * 10)     // 2880 float4 chunks
#define STAGE_ITERS 12                        // ceil(2880/256)

typedef unsigned long long ull;

__device__ __forceinline__ void fma2(ull& d, ull a, ull b) {
    asm("fma.rn.f32x2 %0, %1, %2, %0;" : "+l"(d) : "l"(a), "l"(b));
}
__device__ __forceinline__ ull pack2(float lo, float hi) {
    ull r;
    asm("mov.b64 %0, {%1, %2};" : "=l"(r) : "f"(lo), "f"(hi));
    return r;
}
__device__ __forceinline__ void unpack2(ull v, float& lo, float& hi) {
    asm("mov.b64 {%0, %1}, %2;" : "=f"(lo), "=f"(hi) : "l"(v));
}
__device__ __forceinline__ float fadd(float a, float b) {
    float r;
    asm("add.rn.f32 %0, %1, %2;" : "=f"(r) : "f"(a), "f"(b));
    return r;
}
__device__ __forceinline__ void cp16(unsigned saddr, const void* g) {
    asm volatile("cp.async.cg.shared.global [%0], [%1], 16;"
                 :: "r"(saddr), "l"(g));
}
__device__ __forceinline__ void cp_commit() {
    asm volatile("cp.async.commit_group;");
}
__device__ __forceinline__ void cp_wait0() {
    asm volatile("cp.async.wait_group 0;");
}

__global__ __launch_bounds__(256, 2)
void snn_conv_scan_kernel(const float* __restrict__ x,
                          const float* __restrict__ Wg,
                          const float* __restrict__ bg,
                          float* __restrict__ out)
{
    extern __shared__ float xs[];                 // 2 * BUF_FLOATS
    __shared__ float2 ws[CIN][9][2];              // duplicated weight pairs (2 couts)

    const int tid    = threadIdx.x;
    const int ty     = tid >> 4;          // 0..15 : h within tile
    const int tx     = tid & 15;          // 0..15 : w-pair within tile
    const int tile_h = blockIdx.x & 3;    // 4 tiles of 16 rows
    const int tile_w = blockIdx.x >> 2;   // 2 tiles of 32 cols
    const int c0     = blockIdx.y << 1;   // 32 groups of 2 couts

    const int ht = tile_h * 16;
    const int wt = tile_w * 32;
    const int h0 = ht + ty;
    const int w0 = wt + tx * 2;

    // ---- stage duplicated weights (once): 16*9*2 = 288 entries ----
    for (int i = tid; i < CIN * 9 * 2; i += 256) {
        int c   = i & 1;
        int rem = i >> 1;
        int tap = rem % 9;
        int cin = rem / 9;
        float w = Wg[((c0 + c) * CIN + cin) * 9 + tap];
        ws[cin][tap][c] = make_float2(w, w);
    }

    // ---- zero both x buffers (halos must read as 0.0f forever) ----
    {
        float4* z = reinterpret_cast<float4*>(xs);
        for (int i = tid; i < 2 * BUF_FLOATS / 4; i += 256)
            z[i] = make_float4(0.f, 0.f, 0.f, 0.f);
    }
    __syncthreads();

    // ---- per-thread stage descriptors, reused every t ----
    unsigned xs_u32;
    {
        unsigned long long tmp = __cvta_generic_to_shared(xs);
        xs_u32 = (unsigned)tmp;
    }
    int  goff[STAGE_ITERS];
    int  soff[STAGE_ITERS];
    bool vld[STAGE_ITERS];
    #pragma unroll
    for (int j = 0; j < STAGE_ITERS; ++j) {
        int i = tid + 256 * j;
        int cin = i / 180;
        int rem = i - cin * 180;
        int rr  = rem / 10;
        int k   = rem - rr * 10;
        int gh  = ht - 1 + rr;
        int gc  = wt - 4 + 4 * k;
        bool ok = (i < CHUNKS_PER_T) && (gh >= 0) && (gh < HH) &&
                  (gc >= 0) && (gc + 3 < WWID);
        vld[j]  = ok;
        goff[j] = (cin * (HH * WWID) + gh * WWID + gc) * 4;
        soff[j] = ((cin * ROWS_S + rr) * COLS_S + 4 * k) * 4;
    }

    const float bb0 = bg[c0 + 0];
    const float bb1 = bg[c0 + 1];

    // membrane state: s[cout_local][pixel]
    float s00 = 0.f, s01 = 0.f, s10 = 0.f, s11 = 0.f;

    float* obase = out + (size_t)c0 * (HH * WWID) + h0 * WWID + w0;

    // ---- prologue: stage t = 0 into buffer 0 ----
    {
        const char* src = (const char*)x;
        unsigned sb = xs_u32;
        #pragma unroll
        for (int j = 0; j < STAGE_ITERS; ++j)
            if (vld[j]) cp16(sb + soff[j], src + goff[j]);
        cp_commit();
        cp_wait0();
    }
    __syncthreads();

    #pragma unroll 1
    for (int t = 0; t < T_STEPS; ++t) {
        // kick prefetch of t+1 into the other buffer
        if (t + 1 < T_STEPS) {
            const char* src = (const char*)(x + (size_t)(t + 1) * (CIN * HH * WWID));
            unsigned sb = xs_u32 + ((t + 1) & 1) * (BUF_FLOATS * 4);
            #pragma unroll
            for (int j = 0; j < STAGE_ITERS; ++j)
                if (vld[j]) cp16(sb + soff[j], src + goff[j]);
            cp_commit();
        }

        // conv for t from current buffer (all LDS, no boundary checks)
        const float* cur = xs + (t & 1) * BUF_FLOATS;
        ull a0 = 0ull, a1 = 0ull;

        #pragma unroll
        for (int cin = 0; cin < CIN; ++cin) {
            #pragma unroll
            for (int r = 0; r < 3; ++r) {
                const float* rowp = cur + (cin * ROWS_S + ty + r) * COLS_S + 2 * tx;
                float xm = rowp[3];                                   // col w0-1
                ull  pb  = *reinterpret_cast<const ull*>(rowp + 4);   // cols w0, w0+1
                float xp = rowp[6];                                   // col w0+2

                float x1, x2;
                unpack2(pb, x1, x2);
                ull pa = pack2(xm, x1);   // kw = 0 taps
                ull pc = pack2(x2, xp);   // kw = 2 taps

                // 3 x LDS.128: weight pairs (couts 0,1) for kw = 0,1,2
                const ulonglong2* wv =
                    reinterpret_cast<const ulonglong2*>(&ws[cin][r * 3][0]);
                ulonglong2 wA = wv[0];   // kw=0
                ulonglong2 wB = wv[1];   // kw=1
                ulonglong2 wC = wv[2];   // kw=2

                fma2(a0, pa, wA.x);  fma2(a1, pa, wA.y);
                fma2(a0, pb, wB.x);  fma2(a1, pb, wB.y);
                fma2(a0, pc, wC.x);  fma2(a1, pc, wC.y);
            }
        }

        // LIF update + spike emission; rounding order matches reference.
        float* o = obase + (size_t)t * (COUT * HH * WWID);
        float lo, hi;

        unpack2(a0, lo, hi);
        {
            float cA = fadd(lo, bb0), cB = fadd(hi, bb0);
            float v0 = fadd(s00, cA), v1 = fadd(s01, cB);
            float k0 = (v0 >= 8.f) ? 1.f : 0.f, k1 = (v1 >= 8.f) ? 1.f : 0.f;
            v0 = (v0 >= 8.f) ? 0.f : v0;       v1 = (v1 >= 8.f) ? 0.f : v1;
            s00 = fmaxf(v0, -1.f);             s01 = fmaxf(v1, -1.f);
            *reinterpret_cast<float2*>(o + 0 * (HH * WWID)) = make_float2(k0, k1);
        }
        unpack2(a1, lo, hi);
        {
            float cA = fadd(lo, bb1), cB = fadd(hi, bb1);
            float v0 = fadd(s10, cA), v1 = fadd(s11, cB);
            float k0 = (v0 >= 8.f) ? 1.f : 0.f, k1 = (v1 >= 8.f) ? 1.f : 0.f;
            v0 = (v0 >= 8.f) ? 0.f : v0;       v1 = (v1 >= 8.f) ? 0.f : v1;
            s10 = fmaxf(v0, -1.f);             s11 = fmaxf(v1, -1.f);
            *reinterpret_cast<float2*>(o + 1 * (HH * WWID)) = make_float2(k0, k1);
        }

        // drain the t+1 prefetch, then make the buffer swap safe
        if (t + 1 < T_STEPS) cp_wait0();
        __syncthreads();
    }
}

extern "C" void kernel_launch(void* const* d_in, const int* in_sizes, int n_in,
                              void* d_out, int out_size)
{
    const float* x  = (const float*)d_in[0];   // [128,16,64,64]
    const float* Wg = (const float*)d_in[1];   // [64,16,3,3]
    const float* bg = (const float*)d_in[2];   // [64]
    float* out      = (float*)d_out;           // [128,64,64,64]

    static int attr_set = 0;
    size_t xs_bytes = (size_t)2 * BUF_FLOATS * sizeof(float);   // 92160 B
    if (!attr_set) {
        cudaFuncSetAttribute(snn_conv_scan_kernel,
                             cudaFuncAttributeMaxDynamicSharedMemorySize,
                             (int)xs_bytes);
        attr_set = 1;
    }

    dim3 grid(8, 32);   // 8 spatial tiles (4h x 2w) x 32 cout groups of 2
    snn_conv_scan_kernel<<<grid, 256, xs_bytes>>>(x, Wg, bg, out);
}

// round 5
// speedup vs baseline: 2.6649x; 2.6649x over previous
#include <cuda_runtime.h>

// Two-kernel fused spiking conv2d (T=128, Cin=16, Cout=64, 64x64, pad=1) + LIF.
// K1: conv+bias, t parallel across the grid (16384 blocks) -> full latency
//     hiding. Writes rounded conv_t+b into d_out. Bit-exact (cin,kh,kw) fma2
//     chain identical to the previously passing kernel.
// K2: in-place LIF scan over t per (c,h,w) element of d_out. DRAM-bound.

#define T_STEPS 128
#define CIN     16
#define HH      64
#define WWID    64
#define COUT    64

#define ROWS_S  18              // 16 rows + top/bottom halo
#define COLS_S  40              // fetch span wt-4 .. wt+35 (16B aligned)
#define BUF_FLOATS (CIN * ROWS_S * COLS_S)   // 11520 floats
#define CHUNKS_PER_T (CIN * ROWS_S * 10)     // 2880 float4 chunks
#define STAGE_ITERS 12                        // ceil(2880/256)

typedef unsigned long long ull;

__device__ __forceinline__ void fma2(ull& d, ull a, ull b) {
    asm("fma.rn.f32x2 %0, %1, %2, %0;" : "+l"(d) : "l"(a), "l"(b));
}
__device__ __forceinline__ ull pack2(float lo, float hi) {
    ull r;
    asm("mov.b64 %0, {%1, %2};" : "=l"(r) : "f"(lo), "f"(hi));
    return r;
}
__device__ __forceinline__ void unpack2(ull v, float& lo, float& hi) {
    asm("mov.b64 {%0, %1}, %2;" : "=f"(lo), "=f"(hi) : "l"(v));
}
__device__ __forceinline__ float fadd(float a, float b) {
    float r;
    asm("add.rn.f32 %0, %1, %2;" : "=f"(r) : "f"(a), "f"(b));
    return r;
}
__device__ __forceinline__ void cp16(unsigned saddr, const void* g) {
    asm volatile("cp.async.cg.shared.global [%0], [%1], 16;"
                 :: "r"(saddr), "l"(g));
}
__device__ __forceinline__ void cp_commit() {
    asm volatile("cp.async.commit_group;");
}
__device__ __forceinline__ void cp_wait0() {
    asm volatile("cp.async.wait_group 0;");
}

// ---------------- K1: conv + bias, one (t, cout-group, tile) per block ------
__global__ __launch_bounds__(256, 2)
void conv_kernel(const float* __restrict__ x,
                 const float* __restrict__ Wg,
                 const float* __restrict__ bg,
                 float* __restrict__ out)
{
    extern __shared__ float xs[];                 // BUF_FLOATS
    __shared__ float2 ws[CIN][9][4];              // duplicated weight pairs

    const int tid    = threadIdx.x;
    const int ty     = tid >> 4;          // 0..15 : h within tile
    const int tx     = tid & 15;          // 0..15 : w-pair within tile
    const int tile_h = blockIdx.x & 3;    // 4 tiles of 16 rows
    const int tile_w = blockIdx.x >> 2;   // 2 tiles of 32 cols
    const int c0     = blockIdx.y << 2;   // 16 groups of 4 couts
    const int t      = blockIdx.z;        // timestep

    const int ht = tile_h * 16;
    const int wt = tile_w * 32;
    const int h0 = ht + ty;
    const int w0 = wt + tx * 2;

    // stage duplicated weight pairs
    for (int i = tid; i < CIN * 9 * 4; i += 256) {
        int c   = i & 3;
        int rem = i >> 2;
        int tap = rem % 9;
        int cin = rem / 9;
        float w = Wg[((c0 + c) * CIN + cin) * 9 + tap];
        ws[cin][tap][c] = make_float2(w, w);
    }

    // zero the x buffer (halos must read 0.0f)
    {
        float4* z = reinterpret_cast<float4*>(xs);
        for (int i = tid; i < BUF_FLOATS / 4; i += 256)
            z[i] = make_float4(0.f, 0.f, 0.f, 0.f);
    }
    __syncthreads();

    // stage this block's x tile (one shot)
    unsigned xs_u32;
    {
        unsigned long long tmp = __cvta_generic_to_shared(xs);
        xs_u32 = (unsigned)tmp;
    }
    {
        const char* src = (const char*)(x + (size_t)t * (CIN * HH * WWID));
        #pragma unroll
        for (int j = 0; j < STAGE_ITERS; ++j) {
            int i = tid + 256 * j;
            int cin = i / 180;
            int rem = i - cin * 180;
            int rr  = rem / 10;
            int k   = rem - rr * 10;
            int gh  = ht - 1 + rr;
            int gc  = wt - 4 + 4 * k;
            bool ok = (i < CHUNKS_PER_T) && (gh >= 0) && (gh < HH) &&
                      (gc >= 0) && (gc + 3 < WWID);
            if (ok) {
                int go = (cin * (HH * WWID) + gh * WWID + gc) * 4;
                int so = ((cin * ROWS_S + rr) * COLS_S + 4 * k) * 4;
                cp16(xs_u32 + so, src + go);
            }
        }
        cp_commit();
        cp_wait0();
    }
    __syncthreads();

    ull a0 = 0ull, a1 = 0ull, a2 = 0ull, a3 = 0ull;  // (pix0,pix1) per cout

    #pragma unroll 4
    for (int cin = 0; cin < CIN; ++cin) {
        #pragma unroll
        for (int r = 0; r < 3; ++r) {
            const float* rowp = xs + (cin * ROWS_S + ty + r) * COLS_S + 2 * tx;
            float xm = rowp[3];                                   // col w0-1
            ull  pb  = *reinterpret_cast<const ull*>(rowp + 4);   // w0, w0+1
            float xp = rowp[6];                                   // col w0+2

            float x1, x2;
            unpack2(pb, x1, x2);
            ull pa = pack2(xm, x1);   // kw = 0 taps
            ull pc = pack2(x2, xp);   // kw = 2 taps

            const ulonglong2* wv =
                reinterpret_cast<const ulonglong2*>(&ws[cin][r * 3][0]);
            ulonglong2 wA = wv[0], wA2 = wv[1];  // kw=0: couts {0,1},{2,3}
            ulonglong2 wB = wv[2], wB2 = wv[3];  // kw=1
            ulonglong2 wC = wv[4], wC2 = wv[5];  // kw=2

            fma2(a0, pa, wA.x);  fma2(a1, pa, wA.y);
            fma2(a2, pa, wA2.x); fma2(a3, pa, wA2.y);
            fma2(a0, pb, wB.x);  fma2(a1, pb, wB.y);
            fma2(a2, pb, wB2.x); fma2(a3, pb, wB2.y);
            fma2(a0, pc, wC.x);  fma2(a1, pc, wC.y);
            fma2(a2, pc, wC2.x); fma2(a3, pc, wC2.y);
        }
    }

    // write rounded conv_t + b (matches reference's conv_out = conv + b)
    float* o = out + (size_t)t * (COUT * HH * WWID)
                   + (size_t)c0 * (HH * WWID) + h0 * WWID + w0;
    const float bb0 = bg[c0 + 0];
    const float bb1 = bg[c0 + 1];
    const float bb2 = bg[c0 + 2];
    const float bb3 = bg[c0 + 3];
    float lo, hi;
    unpack2(a0, lo, hi);
    *reinterpret_cast<float2*>(o + 0 * (HH * WWID)) =
        make_float2(fadd(lo, bb0), fadd(hi, bb0));
    unpack2(a1, lo, hi);
    *reinterpret_cast<float2*>(o + 1 * (HH * WWID)) =
        make_float2(fadd(lo, bb1), fadd(hi, bb1));
    unpack2(a2, lo, hi);
    *reinterpret_cast<float2*>(o + 2 * (HH * WWID)) =
        make_float2(fadd(lo, bb2), fadd(hi, bb2));
    unpack2(a3, lo, hi);
    *reinterpret_cast<float2*>(o + 3 * (HH * WWID)) =
        make_float2(fadd(lo, bb3), fadd(hi, bb3));
}

// ---------------- K2: in-place LIF scan over t ------------------------------
__global__ __launch_bounds__(256)
void scan_kernel(float* __restrict__ out)
{
    const int idx = blockIdx.x * 256 + threadIdx.x;   // (c,h,w) element
    float* p = out + idx;

    float s = 0.f;
    #pragma unroll 4
    for (int t = 0; t < T_STEPS; ++t) {
        float c = p[(size_t)t * (COUT * HH * WWID)];
        float v = fadd(s, c);                 // state + conv_t (rounded)
        float k = (v >= 8.f) ? 1.f : 0.f;
        v = (v >= 8.f) ? 0.f : v;             // reset-to-value
        s = fmaxf(v, -1.f);                   // Threshold(-1, -1)
        p[(size_t)t * (COUT * HH * WWID)] = k;
    }
}

extern "C" void kernel_launch(void* const* d_in, const int* in_sizes, int n_in,
                              void* d_out, int out_size)
{
    const float* x  = (const float*)d_in[0];   // [128,16,64,64]
    const float* Wg = (const float*)d_in[1];   // [64,16,3,3]
    const float* bg = (const float*)d_in[2];   // [64]
    float* out      = (float*)d_out;           // [128,64,64,64]

    static int attr_set = 0;
    size_t xs_bytes = (size_t)BUF_FLOATS * sizeof(float);   // 46080 B
    if (!attr_set) {
        cudaFuncSetAttribute(conv_kernel,
                             cudaFuncAttributeMaxDynamicSharedMemorySize,
                             (int)xs_bytes);
        attr_set = 1;
    }

    dim3 grid1(8, 16, T_STEPS);   // spatial tiles x cout groups x timesteps
    conv_kernel<<<grid1, 256, xs_bytes>>>(x, Wg, bg, out);

    scan_kernel<<<(COUT * HH * WWID) / 256, 256>>>(out);
}